// round 10
// baseline (speedup 1.0000x reference)
#include <cuda_runtime.h>
#include <cuda_bf16.h>
#include <cstdint>
#include <cstddef>

// RNN_5188320494079: N=64, T=1024, D=256, H=256, fp32.
// Inputs: x[N,T,D], h0[N,H], Wx[D,H], Wh[H,H], b[H]. Output: [N,T,H].
//
// Kernel 1: Out = x @ Wx + b (packed-f32x2 SGEMM, in-place into d_out).
// Kernel 2: partial-sum-exchange cluster scan. 128 CTAs, cluster(2) = batch n.
//   CTA r owns h rows/cols [r*128,+128) and ONLY ever reads its own h-half.
//   256 threads, one Wh column each (128 rows x 1 col = 64 packed regs):
//     threads   0..127 compute partials for the PEER's columns and ship them
//                      via st.async+complete_tx (512B/step),
//     threads 128..255 compute partials for OWN columns, receive the peer's
//                      partials, add xw, tanh, store h locally + output.
//   No h exchange, no cross-thread reduction, one __syncthreads per step.

#define RNN_N 64
#define RNN_T 1024
#define RNN_D 256
#define RNN_H 256
#define HHALF 128

typedef unsigned long long ull;

__device__ __forceinline__ void ffma2(ull& d, ull a, ull b) {
    asm("fma.rn.f32x2 %0, %1, %2, %0;" : "+l"(d) : "l"(a), "l"(b));
}
__device__ __forceinline__ float2 u2f(ull u) {
    float2 f;
    asm("mov.b64 {%0, %1}, %2;" : "=f"(f.x), "=f"(f.y) : "l"(u));
    return f;
}
__device__ __forceinline__ ull f2u(float a, float b) {
    ull u;
    asm("mov.b64 %0, {%1, %2};" : "=l"(u) : "f"(a), "f"(b));
    return u;
}
__device__ __forceinline__ uint32_t smem_u32(const void* p) {
    uint32_t a;
    asm("{ .reg .u64 t; cvta.to.shared.u64 t, %1; cvt.u32.u64 %0, t; }"
        : "=r"(a) : "l"(p));
    return a;
}
__device__ __forceinline__ void mbar_wait(uint32_t addr, uint32_t parity) {
    asm volatile(
        "{\n\t.reg .pred P;\n\t"
        "WL%=:\n\t"
        "mbarrier.try_wait.parity.acquire.cta.shared::cta.b64 P, [%0], %1, 0x989680;\n\t"
        "@P bra.uni WD%=;\n\t"
        "bra.uni WL%=;\n\t"
        "WD%=:\n\t}"
        :: "r"(addr), "r"(parity) : "memory");
}
__device__ __forceinline__ void mbar_expect(uint32_t addr, uint32_t bytes) {
    asm volatile("mbarrier.arrive.expect_tx.shared::cta.b64 _, [%0], %1;"
                 :: "r"(addr), "r"(bytes) : "memory");
}

// ---------------------------------------------------------------------------
// Kernel 1: smem-tiled SGEMM, BM=128 BN=128 BK=16, 256 thr, f32x2 micro-kernel.
// (unchanged — FFMA2-bound, ~180us)
// ---------------------------------------------------------------------------
__global__ __launch_bounds__(256, 2)
void gemm_xw_kernel(const float* __restrict__ X, const float* __restrict__ Wx,
                    const float* __restrict__ bias, float* __restrict__ Out) {
    __shared__ __align__(16) float2 Asd[16][128];
    __shared__ __align__(16) float  Bs[16][128];

    const int tid = threadIdx.x;
    const int tx = tid & 15;
    const int ty = tid >> 4;
    const int m0 = blockIdx.x * 128;
    const int n0 = blockIdx.y * 128;

    const int a_row = tid >> 2;
    const int a_col = (tid & 3) << 2;
    const int b_row = tid >> 5;
    const int b_col = (tid & 31) << 2;

    ull acc[8][4];
#pragma unroll
    for (int i = 0; i < 8; i++)
#pragma unroll
        for (int j = 0; j < 4; j++) acc[i][j] = 0ull;

    const float* Xa0 = &X[(size_t)(m0 + a_row) * RNN_D + a_col];
    const float* Xa1 = &X[(size_t)(m0 + a_row + 64) * RNN_D + a_col];
    const float* Wb0 = &Wx[(size_t)b_row * RNN_H + n0 + b_col];
    const float* Wb1 = &Wx[(size_t)(b_row + 8) * RNN_H + n0 + b_col];

    for (int k0 = 0; k0 < RNN_D; k0 += 16) {
        float4 av0 = __ldcs(reinterpret_cast<const float4*>(Xa0 + k0));
        float4 av1 = __ldcs(reinterpret_cast<const float4*>(Xa1 + k0));
        float4 bv0 = *reinterpret_cast<const float4*>(Wb0 + (size_t)k0 * RNN_H);
        float4 bv1 = *reinterpret_cast<const float4*>(Wb1 + (size_t)k0 * RNN_H);
        __syncthreads();
        Asd[a_col + 0][a_row] = make_float2(av0.x, av0.x);
        Asd[a_col + 1][a_row] = make_float2(av0.y, av0.y);
        Asd[a_col + 2][a_row] = make_float2(av0.z, av0.z);
        Asd[a_col + 3][a_row] = make_float2(av0.w, av0.w);
        Asd[a_col + 0][a_row + 64] = make_float2(av1.x, av1.x);
        Asd[a_col + 1][a_row + 64] = make_float2(av1.y, av1.y);
        Asd[a_col + 2][a_row + 64] = make_float2(av1.z, av1.z);
        Asd[a_col + 3][a_row + 64] = make_float2(av1.w, av1.w);
        *reinterpret_cast<float4*>(&Bs[b_row][b_col]) = bv0;
        *reinterpret_cast<float4*>(&Bs[b_row + 8][b_col]) = bv1;
        __syncthreads();
#pragma unroll
        for (int k = 0; k < 16; k++) {
            const ulonglong2* ad = reinterpret_cast<const ulonglong2*>(&Asd[k][ty * 8]);
            ulonglong2 aa0 = ad[0], aa1 = ad[1], aa2 = ad[2], aa3 = ad[3];
            const ulonglong2* bd = reinterpret_cast<const ulonglong2*>(&Bs[k][tx * 8]);
            ulonglong2 bb0 = bd[0], bb1 = bd[1];
            ull ap[8] = {aa0.x, aa0.y, aa1.x, aa1.y, aa2.x, aa2.y, aa3.x, aa3.y};
            ull bp[4] = {bb0.x, bb0.y, bb1.x, bb1.y};
#pragma unroll
            for (int i = 0; i < 8; i++) {
                ffma2(acc[i][0], ap[i], bp[0]);
                ffma2(acc[i][1], ap[i], bp[1]);
                ffma2(acc[i][2], ap[i], bp[2]);
                ffma2(acc[i][3], ap[i], bp[3]);
            }
        }
    }

    float4 bb0 = *reinterpret_cast<const float4*>(&bias[n0 + tx * 8]);
    float4 bb1 = *reinterpret_cast<const float4*>(&bias[n0 + tx * 8 + 4]);
    float bb[8] = {bb0.x, bb0.y, bb0.z, bb0.w, bb1.x, bb1.y, bb1.z, bb1.w};
#pragma unroll
    for (int i = 0; i < 8; i++) {
        size_t r = (size_t)(m0 + ty * 8 + i) * RNN_H + n0 + tx * 8;
        float2 v0 = u2f(acc[i][0]), v1 = u2f(acc[i][1]);
        float2 v2 = u2f(acc[i][2]), v3 = u2f(acc[i][3]);
        float4 o0 = make_float4(v0.x + bb[0], v0.y + bb[1], v1.x + bb[2], v1.y + bb[3]);
        float4 o1 = make_float4(v2.x + bb[4], v2.y + bb[5], v3.x + bb[6], v3.y + bb[7]);
        *reinterpret_cast<float4*>(&Out[r]) = o0;
        *reinterpret_cast<float4*>(&Out[r + 4]) = o1;
    }
}

// ---------------------------------------------------------------------------
// Kernel 2: partial-exchange cluster scan (see header comment).
// Protocol per step t (double-buffered tx barriers B[0], B[1]):
//   all threads:  p = sum over OWN 128 h rows of hbuf[cur] (64 FFMA2, Wh in
//                 regs). Senders' cols = peer's own cols; finalizers' = mine.
//   senders (tid<128):    st.async p -> peer qbuf[t&1][tid], peer B[t&1].
//   finalizers (tid>=128): wait B[t&1] parity (t>>1)&1; tid==128 re-arms
//                 B[t&1] (+512B) for step t+2; z = xw + p + qbuf[t&1][l];
//                 h = tanh(z); hbuf[nxt][l] = h; out[t][col] = h.
//   __syncthreads(); cur ^= 1.
// Sends of consecutive steps target ALTERNATE barriers; re-arm at step t
// precedes (via the step-t syncthreads and the fabric causal chain) any
// step-t+2 arrival. h never crosses the fabric; only 512B of partials do.
// ---------------------------------------------------------------------------
__global__ __launch_bounds__(256, 1) __cluster_dims__(2, 1, 1)
void rnn_scan_kernel(const float* __restrict__ h0,
                     const float* __restrict__ Wh,
                     float* Out) {
    __shared__ __align__(16) float hbuf[2][HHALF];   // own h half, 1KB
    __shared__ __align__(16) float qbuf[2][HHALF];   // peer partials, 1KB
    __shared__ __align__(8)  unsigned long long mbars[2]; // B0, B1

    const int tid = threadIdx.x;
    uint32_t rank;
    asm("mov.u32 %0, %%cluster_ctarank;" : "=r"(rank));
    const uint32_t peer = rank ^ 1u;
    const int n = blockIdx.x >> 1;
    const int own_base = (int)rank * HHALF;
    const int peer_base = (int)peer * HHALF;
    const bool is_sender = (tid < HHALF);
    const int l = tid & (HHALF - 1);             // local slot
    const int col = is_sender ? (peer_base + l) : (own_base + l);

    const uint32_t mbarB0 = smem_u32((const void*)&mbars[0]);
    const uint32_t mbarB1 = smem_u32((const void*)&mbars[1]);

    if (tid == 0) {
        asm volatile("mbarrier.init.shared.b64 [%0], %1;"
                     :: "r"(mbarB0), "r"(1) : "memory");
        asm volatile("mbarrier.init.shared.b64 [%0], %1;"
                     :: "r"(mbarB1), "r"(1) : "memory");
    }

    // Register-resident Wh column slice: own rows x my col, 64 packed pairs.
    // wq[k] = {Wh[own_base+2k][col], Wh[own_base+2k+1][col]}
    ull wq[64];
#pragma unroll
    for (int k = 0; k < 64; k++) {
        wq[k] = f2u(__ldg(&Wh[(size_t)(own_base + 2 * k) * RNN_H + col]),
                    __ldg(&Wh[(size_t)(own_base + 2 * k + 1) * RNN_H + col]));
    }

    float* outn = Out + (size_t)n * RNN_T * RNN_H;

    if (tid < HHALF)
        hbuf[0][tid] = h0[(size_t)n * RNN_H + own_base + tid];

    // sender: remote qbuf slots + remote barriers; finalizer: xw stream
    float xw_cur = 0.f;
    uint32_t rQ0 = 0, rQ1 = 0, rmB0 = 0, rmB1 = 0;
    if (is_sender) {
        uint32_t q0 = smem_u32(&qbuf[0][l]);
        uint32_t q1 = smem_u32(&qbuf[1][l]);
        asm("mapa.shared::cluster.u32 %0, %1, %2;" : "=r"(rQ0) : "r"(q0), "r"(peer));
        asm("mapa.shared::cluster.u32 %0, %1, %2;" : "=r"(rQ1) : "r"(q1), "r"(peer));
        asm("mapa.shared::cluster.u32 %0, %1, %2;" : "=r"(rmB0) : "r"(mbarB0), "r"(peer));
        asm("mapa.shared::cluster.u32 %0, %1, %2;" : "=r"(rmB1) : "r"(mbarB1), "r"(peer));
    } else {
        xw_cur = __ldcg(&outn[col]);
    }
    __syncthreads();
    if (tid == 0) {
        mbar_expect(mbarB0, 512u);   // phase consumed at t=0
        mbar_expect(mbarB1, 512u);   // phase consumed at t=1
    }
    // barriers + h0 visible cluster-wide before any remote st.async
    asm volatile("barrier.cluster.arrive.aligned;" ::: "memory");
    asm volatile("barrier.cluster.wait.aligned;" ::: "memory");

    int cur = 0;
    for (int t = 0; t < RNN_T; t++) {
        float xw_nxt = 0.f;
        if (!is_sender && t + 1 < RNN_T)
            xw_nxt = __ldcg(&outn[(size_t)(t + 1) * RNN_H + col]);

        // p = sum over own 128 h rows (64 packed FFMA2, broadcast LDS.128)
        const ulonglong2* hp = reinterpret_cast<const ulonglong2*>(&hbuf[cur][0]);
        ull a0 = 0ull, a1 = 0ull, a2 = 0ull, a3 = 0ull;
#pragma unroll
        for (int m = 0; m < 16; m++) {
            ulonglong2 hv = hp[2 * m];
            ulonglong2 hw = hp[2 * m + 1];
            ffma2(a0, hv.x, wq[4 * m + 0]);
            ffma2(a1, hv.y, wq[4 * m + 1]);
            ffma2(a2, hw.x, wq[4 * m + 2]);
            ffma2(a3, hw.y, wq[4 * m + 3]);
        }
        float2 f0 = u2f(a0), f1 = u2f(a1), f2 = u2f(a2), f3 = u2f(a3);
        float p = ((f0.x + f0.y) + (f1.x + f1.y)) +
                  ((f2.x + f2.y) + (f3.x + f3.y));

        if (is_sender) {
            // ship partial for peer's column; signals peer B[t&1] (+4B)
            uint32_t ra = (t & 1) ? rQ1 : rQ0;
            uint32_t rb = (t & 1) ? rmB1 : rmB0;
            asm volatile(
                "st.async.shared::cluster.mbarrier::complete_tx::bytes.b32 [%0], %1, [%2];"
                :: "r"(ra), "f"(p), "r"(rb) : "memory");
        } else {
            const uint32_t bw = (t & 1) ? mbarB1 : mbarB0;
            mbar_wait(bw, (uint32_t)(t >> 1) & 1u);      // peer partials landed
            if (tid == HHALF && t + 2 < RNN_T)           // re-arm for step t+2
                mbar_expect(bw, 512u);
            float z = xw_cur + p + qbuf[t & 1][l];
            float e = __expf(2.0f * z);                  // tanh via MUFU
            float hn = 1.0f - __fdividef(2.0f, e + 1.0f);
            hbuf[cur ^ 1][l] = hn;                       // own h half, local only
            __stcs(&outn[(size_t)t * RNN_H + col], hn);  // overwrite xW slot
            xw_cur = xw_nxt;
        }
        __syncthreads();   // h_{t+1} own half visible to all; qbuf phase done
        cur ^= 1;
    }

    // keep SMEM alive until all remote traffic has drained cluster-wide
    asm volatile("barrier.cluster.arrive.aligned;" ::: "memory");
    asm volatile("barrier.cluster.wait.aligned;" ::: "memory");
}

// ---------------------------------------------------------------------------
extern "C" void kernel_launch(void* const* d_in, const int* in_sizes, int n_in,
                              void* d_out, int out_size) {
    const float* x  = (const float*)d_in[0];   // [N,T,D]
    const float* h0 = (const float*)d_in[1];   // [N,H]
    const float* Wx = (const float*)d_in[2];   // [D,H]
    const float* Wh = (const float*)d_in[3];   // [H,H]
    const float* b  = (const float*)d_in[4];   // [H]
    float* out = (float*)d_out;                // [N,T,H]

    (void)in_sizes; (void)n_in; (void)out_size;

    dim3 g1((RNN_N * RNN_T) / 128, RNN_H / 128);
    gemm_xw_kernel<<<g1, 256>>>(x, Wx, b, out);

    rnn_scan_kernel<<<RNN_N * 2, 256>>>(h0, Wh, out);
}